// round 5
// baseline (speedup 1.0000x reference)
#include <cuda_runtime.h>

#define NN 100000
#define EE 1000000
#define CC 64
#define OUTC 40
#define NB 98        // ceil(NN/1024)
#define E4 (EE/4)

typedef unsigned long long ull;

// ---------------- device scratch ----------------
__device__ int   g_cc[2 * NN];     // [0,NN): degree count ; [NN,2NN): fill cursor
__device__ int   g_rowptr[NN];     // within-block exclusive prefix (scanA)
__device__ int   g_bsum[NB];       // per-block sums -> exclusive block offsets (scanB)
__device__ int2  g_edge[EE];       // {src, bitcast(norm)} grouped by dst
__device__ float g_h2[NN * CC];    // conv1 output (post-relu)

// ---------------- f32x2 helpers ----------------
__device__ __forceinline__ ull pack2(float v) {
    ull r; asm("mov.b64 %0, {%1, %1};" : "=l"(r) : "f"(v)); return r;
}
__device__ __forceinline__ void fma2(ull& d, ull a, ull b) {
    asm("fma.rn.f32x2 %0, %1, %2, %0;" : "+l"(d) : "l"(a), "l"(b));
}
__device__ __forceinline__ void unpack2(ull v, float& lo, float& hi) {
    asm("mov.b64 {%0, %1}, %2;" : "=f"(lo), "=f"(hi) : "l"(v));
}

// ---------------- edge-dtype detect (per-block, uniform) ----------------
__device__ __forceinline__ int block_is64(const void* ei, int* s_flag) {
    if (threadIdx.x == 0) {
        const long long* p = (const long long*)ei;
        int ok = 1;
#pragma unroll
        for (int i = 0; i < 16; i++) { long long v = p[i]; if (v < 0 || v >= NN) ok = 0; }
        *s_flag = ok;
    }
    __syncthreads();
    return *s_flag;
}

// ---------------- CSR build ----------------
__global__ __launch_bounds__(256) void k_hist(const void* __restrict__ ei) {
    __shared__ int s_is64;
    int is64 = block_is64(ei, &s_is64);
    int i = blockIdx.x * 256 + threadIdx.x;
    if (i >= E4) return;
    if (!is64) {
        int4 d = ((const int4*)ei)[E4 + i];
        atomicAdd(&g_cc[d.x], 1); atomicAdd(&g_cc[d.y], 1);
        atomicAdd(&g_cc[d.z], 1); atomicAdd(&g_cc[d.w], 1);
    } else {
        const long long* p = (const long long*)ei;
#pragma unroll
        for (int j = 0; j < 4; j++) atomicAdd(&g_cc[(int)p[EE + 4 * i + j]], 1);
    }
}

__global__ void k_scanA() {
    __shared__ int s[1024];
    int i = blockIdx.x * 1024 + threadIdx.x;
    int v = (i < NN) ? g_cc[i] : 0;
    s[threadIdx.x] = v;
    __syncthreads();
    for (int off = 1; off < 1024; off <<= 1) {
        int t = (threadIdx.x >= off) ? s[threadIdx.x - off] : 0;
        __syncthreads();
        s[threadIdx.x] += t;
        __syncthreads();
    }
    if (i < NN) g_rowptr[i] = s[threadIdx.x] - v;   // exclusive within block
    if (threadIdx.x == 1023) g_bsum[blockIdx.x] = s[1023];
}

__global__ void k_scanB() {   // 128 threads, exclusive scan of 98 block sums
    int tid = threadIdx.x, lane = tid & 31, wid = tid >> 5;
    int v = (tid < NB) ? g_bsum[tid] : 0;
    int x = v;
#pragma unroll
    for (int off = 1; off < 32; off <<= 1) {
        int y = __shfl_up_sync(0xffffffffu, x, off);
        if (lane >= off) x += y;
    }
    __shared__ int wsum[4];
    if (lane == 31) wsum[wid] = x;
    __syncthreads();
    int woff = 0;
#pragma unroll
    for (int w = 0; w < 4; w++) if (w < wid) woff += wsum[w];
    if (tid < NB) g_bsum[tid] = x - v + woff;       // global exclusive
}

__device__ __forceinline__ void fill_one(int s, int d) {
    float ns = rsqrtf((float)g_cc[s] + 1.0f);
    float nd = rsqrtf((float)g_cc[d] + 1.0f);
    int pos = g_rowptr[d] + g_bsum[d >> 10] + atomicAdd(&g_cc[NN + d], 1);
    g_edge[pos] = make_int2(s, __float_as_int(ns * nd));
}

__global__ __launch_bounds__(256) void k_fill(const void* __restrict__ ei) {
    __shared__ int s_is64;
    int is64 = block_is64(ei, &s_is64);
    int i = blockIdx.x * 256 + threadIdx.x;
    if (i >= E4) return;
    if (!is64) {
        int4 s4 = ((const int4*)ei)[i];
        int4 d4 = ((const int4*)ei)[E4 + i];
        fill_one(s4.x, d4.x); fill_one(s4.y, d4.y);
        fill_one(s4.z, d4.z); fill_one(s4.w, d4.w);
    } else {
        const long long* p = (const long long*)ei;
#pragma unroll
        for (int j = 0; j < 4; j++)
            fill_one((int)p[4 * i + j], (int)p[EE + 4 * i + j]);
    }
}

// ---------------- gather: 8 lanes per node, f32x2 accumulate ----------------
__device__ __forceinline__ void gather_node(const float* __restrict__ h, int node,
                                            ull acc[4]) {
    int l = threadIdx.x & 7;                   // lane within node-group
    int cnt = g_cc[node];
    float self = __frcp_rn((float)cnt + 1.0f); // dinv^2
    const ulonglong2* row = (const ulonglong2*)(h + (size_t)node * CC);
    ulonglong2 ra = row[2 * l], rb = row[2 * l + 1];
    ull s2 = pack2(self);
    acc[0] = acc[1] = acc[2] = acc[3] = 0ull;
    fma2(acc[0], ra.x, s2); fma2(acc[1], ra.y, s2);
    fma2(acc[2], rb.x, s2); fma2(acc[3], rb.y, s2);

    int beg = g_rowptr[node] + g_bsum[node >> 10];
    int end = (node + 1 == NN) ? EE : (g_rowptr[node + 1] + g_bsum[(node + 1) >> 10]);

    int e = beg;
    for (; e + 1 < end; e += 2) {
        int2 m0 = g_edge[e], m1 = g_edge[e + 1];
        const ulonglong2* r0 = (const ulonglong2*)(h + (size_t)m0.x * CC);
        const ulonglong2* r1 = (const ulonglong2*)(h + (size_t)m1.x * CC);
        ulonglong2 a0 = r0[2 * l], b0 = r0[2 * l + 1];
        ulonglong2 a1 = r1[2 * l], b1 = r1[2 * l + 1];
        ull n0 = pack2(__int_as_float(m0.y));
        ull n1 = pack2(__int_as_float(m1.y));
        fma2(acc[0], a0.x, n0); fma2(acc[1], a0.y, n0);
        fma2(acc[2], b0.x, n0); fma2(acc[3], b0.y, n0);
        fma2(acc[0], a1.x, n1); fma2(acc[1], a1.y, n1);
        fma2(acc[2], b1.x, n1); fma2(acc[3], b1.y, n1);
    }
    if (e < end) {
        int2 m = g_edge[e];
        const ulonglong2* r0 = (const ulonglong2*)(h + (size_t)m.x * CC);
        ulonglong2 a0 = r0[2 * l], b0 = r0[2 * l + 1];
        ull n0 = pack2(__int_as_float(m.y));
        fma2(acc[0], a0.x, n0); fma2(acc[1], a0.y, n0);
        fma2(acc[2], b0.x, n0); fma2(acc[3], b0.y, n0);
    }
}

__device__ __forceinline__ void store_v(float* vbuf, ull acc[4]) {
    int nl = threadIdx.x >> 3, l = threadIdx.x & 7;
    ulonglong2* p = (ulonglong2*)(vbuf + nl * 68 + l * 8);
    p[0] = make_ulonglong2(acc[0], acc[1]);
    p[1] = make_ulonglong2(acc[2], acc[3]);
}

// ---------------- GEMV from shared: 8 threads x 8 cols per node ----------------
template <bool RELU>
__device__ __forceinline__ void gemv64(const float* __restrict__ v,
                                       const float* __restrict__ W,
                                       const float* __restrict__ bias,
                                       float* __restrict__ o /* 8 floats dest */) {
    int n = threadIdx.x >> 3;
    int j0 = (threadIdx.x & 7) * 8;
    const float* vr = v + n * 68;
    ull acc[4] = {0ull, 0ull, 0ull, 0ull};
#pragma unroll 8
    for (int k = 0; k < CC; k++) {
        ull xk = pack2(vr[k]);
        const ulonglong2* w2 = (const ulonglong2*)(W + k * CC + j0);
        ulonglong2 wa = w2[0], wb = w2[1];
        fma2(acc[0], xk, wa.x); fma2(acc[1], xk, wa.y);
        fma2(acc[2], xk, wb.x); fma2(acc[3], xk, wb.y);
    }
#pragma unroll
    for (int j = 0; j < 4; j++) {
        float lo, hi;
        unpack2(acc[j], lo, hi);
        lo += bias[j0 + 2 * j];
        hi += bias[j0 + 2 * j + 1];
        if (RELU) { lo = fmaxf(lo, 0.f); hi = fmaxf(hi, 0.f); }
        o[2 * j] = lo; o[2 * j + 1] = hi;
    }
}

// ---------------- fused conv1: h2 = relu(agg(x) @ W1 + b1) ----------------
__global__ __launch_bounds__(256)
void k_fuse1(const float* __restrict__ x, const float* __restrict__ W1,
             const float* __restrict__ b1) {
    __shared__ __align__(16) float Ws[CC * CC];
    __shared__ float bs[CC];
    __shared__ __align__(16) float vbuf[32 * 68];
    int t = threadIdx.x;
    for (int idx = t; idx < CC * CC; idx += 256) Ws[idx] = W1[idx];
    if (t < CC) bs[t] = b1[t];

    int node = blockIdx.x * 32 + (t >> 3);
    ull acc[4];
    gather_node(x, node, acc);
    store_v(vbuf, acc);
    __syncthreads();

    float o[8];
    gemv64<true>(vbuf, Ws, bs, o);
    float* dst = g_h2 + (size_t)node * CC + (t & 7) * 8;
    ((float4*)dst)[0] = make_float4(o[0], o[1], o[2], o[3]);
    ((float4*)dst)[1] = make_float4(o[4], o[5], o[6], o[7]);
}

// ---------------- fused conv2+MLP: out = ((agg(h2)@W2+b2)@Wm1+bm1,relu)@Wm2+bm2 ----------------
__global__ __launch_bounds__(256)
void k_fuse2(float* __restrict__ out,
             const float* __restrict__ W2,  const float* __restrict__ b2,
             const float* __restrict__ Wm1, const float* __restrict__ bm1,
             const float* __restrict__ Wm2, const float* __restrict__ bm2) {
    __shared__ __align__(16) float Ws[CC * CC];
    __shared__ float bs[CC];
    __shared__ __align__(16) float vbuf[32 * 68];
    __shared__ __align__(16) float tbuf[32 * 68];
    int t = threadIdx.x;
    int n = t >> 3;

    for (int idx = t; idx < CC * CC; idx += 256) Ws[idx] = W2[idx];
    if (t < CC) bs[t] = b2[t];

    int node = blockIdx.x * 32 + n;
    ull acc[4];
    gather_node(g_h2, node, acc);
    store_v(vbuf, acc);
    __syncthreads();

    // stage 1: t1 = v @ W2 + b2
    {
        float o[8];
        gemv64<false>(vbuf, Ws, bs, o);
        float* d = tbuf + n * 68 + (t & 7) * 8;
        ((float4*)d)[0] = make_float4(o[0], o[1], o[2], o[3]);
        ((float4*)d)[1] = make_float4(o[4], o[5], o[6], o[7]);
    }
    __syncthreads();

    // swap weights -> Wm1
    for (int idx = t; idx < CC * CC; idx += 256) Ws[idx] = Wm1[idx];
    if (t < CC) bs[t] = bm1[t];
    __syncthreads();

    // stage 2: t2 = relu(t1 @ Wm1 + bm1)  (write back into vbuf)
    {
        float o[8];
        gemv64<true>(tbuf, Ws, bs, o);
        float* d = vbuf + n * 68 + (t & 7) * 8;
        ((float4*)d)[0] = make_float4(o[0], o[1], o[2], o[3]);
        ((float4*)d)[1] = make_float4(o[4], o[5], o[6], o[7]);
    }
    __syncthreads();

    // swap weights -> Wm2 (64 x 40)
    for (int idx = t; idx < CC * OUTC; idx += 256) Ws[idx] = Wm2[idx];
    if (t < OUTC) bs[t] = bm2[t];
    __syncthreads();

    // stage 3: out = t2 @ Wm2 + bm2   (8 threads x 5 cols per node)
    {
        int j0 = (t & 7) * 5;
        const float* vr = vbuf + n * 68;
        float a0 = 0.f, a1 = 0.f, a2 = 0.f, a3 = 0.f, a4 = 0.f;
#pragma unroll 8
        for (int k = 0; k < CC; k++) {
            float xk = vr[k];
            const float* w = Ws + k * OUTC + j0;
            a0 = fmaf(xk, w[0], a0); a1 = fmaf(xk, w[1], a1);
            a2 = fmaf(xk, w[2], a2); a3 = fmaf(xk, w[3], a3);
            a4 = fmaf(xk, w[4], a4);
        }
        float* d = out + (size_t)node * OUTC + j0;
        d[0] = a0 + bs[j0];     d[1] = a1 + bs[j0 + 1];
        d[2] = a2 + bs[j0 + 2]; d[3] = a3 + bs[j0 + 3];
        d[4] = a4 + bs[j0 + 4];
    }
}

// ---------------- launcher ----------------
extern "C" void kernel_launch(void* const* d_in, const int* in_sizes, int n_in,
                              void* d_out, int out_size) {
    const float* x   = (const float*)d_in[0];
    const void*  ei  = d_in[1];
    const float* W1  = (const float*)d_in[2];
    const float* b1  = (const float*)d_in[3];
    const float* W2  = (const float*)d_in[4];
    const float* b2  = (const float*)d_in[5];
    const float* Wm1 = (const float*)d_in[6];
    const float* bm1 = (const float*)d_in[7];
    const float* Wm2 = (const float*)d_in[8];
    const float* bm2 = (const float*)d_in[9];
    float* out = (float*)d_out;

    void* pcc = nullptr;
    cudaGetSymbolAddress(&pcc, g_cc);

    const int GE = (E4 + 255) / 256;     // 977
    const int GF = NN / 32;              // 3125

    cudaMemsetAsync(pcc, 0, 2 * NN * sizeof(int));
    k_hist <<<GE, 256>>>(ei);
    k_scanA<<<NB, 1024>>>();
    k_scanB<<<1, 128>>>();
    k_fill <<<GE, 256>>>(ei);
    k_fuse1<<<GF, 256>>>(x, W1, b1);
    k_fuse2<<<GF, 256>>>(out, W2, b2, Wm1, bm1, Wm2, bm2);
}

// round 6
// speedup vs baseline: 1.3365x; 1.3365x over previous
#include <cuda_runtime.h>
#include <cuda_fp16.h>

#define NN 100000
#define EE 1000000
#define CC 64
#define OUTC 40
#define NB 98          // ceil(NN/1024)
#define E4 (EE/4)
#define CSRG 592       // resident grid: 148 SMs x 8 blocks guaranteed by launch_bounds
#define CSRT 256

typedef unsigned long long ull;

// ---------------- device scratch ----------------
__device__ int     g_cc[2 * NN + 4];   // [0,NN) counts ; [NN,2NN) cursors ; [2NN] barrier
__device__ int     g_rowptr[NN];
__device__ int     g_bsum[NB];
__device__ int2    g_edge[EE];         // {src, bitcast(norm)} grouped by dst
__device__ __half2 g_hf[NN * CC / 2];  // fp16 feature rows (gather input)
__device__ float   g_h2[NN * CC];      // fp32 feature rows

// ---------------- f32x2 helpers ----------------
__device__ __forceinline__ ull pack2(float v) {
    ull r; asm("mov.b64 %0, {%1, %1};" : "=l"(r) : "f"(v)); return r;
}
__device__ __forceinline__ void fma2(ull& d, ull a, ull b) {
    asm("fma.rn.f32x2 %0, %1, %2, %0;" : "+l"(d) : "l"(a), "l"(b));
}
__device__ __forceinline__ void unpack2(ull v, float& lo, float& hi) {
    asm("mov.b64 {%0, %1}, %2;" : "=f"(lo), "=f"(hi) : "l"(v));
}

// ---------------- fused CSR build: hist -> scan -> fill, one kernel ----------------
__device__ __forceinline__ void gsync(int target) {
    __threadfence();
    __syncthreads();
    if (threadIdx.x == 0) {
        atomicAdd(&g_cc[2 * NN], 1);
        while (atomicAdd(&g_cc[2 * NN], 0) < target) __nanosleep(64);
        __threadfence();
    }
    __syncthreads();
}

__device__ __forceinline__ void fill_one(int s, int d) {
    float ns = rsqrtf((float)g_cc[s] + 1.0f);
    float nd = rsqrtf((float)g_cc[d] + 1.0f);
    int pos = g_rowptr[d] + g_bsum[d >> 10] + atomicAdd(&g_cc[NN + d], 1);
    g_edge[pos] = make_int2(s, __float_as_int(ns * nd));
}

__global__ __launch_bounds__(CSRT, 8)
void k_csr(const void* __restrict__ ei) {
    __shared__ int s_is64;
    __shared__ int s_scan[CSRT];
    int tid = threadIdx.x, bid = blockIdx.x;

    if (tid == 0) {
        const long long* p = (const long long*)ei;
        int ok = 1;
#pragma unroll
        for (int i = 0; i < 16; i++) { long long v = p[i]; if (v < 0 || v >= NN) ok = 0; }
        s_is64 = ok;
    }
    __syncthreads();
    int is64 = s_is64;

    // Phase A: degree histogram
    for (int i = bid * CSRT + tid; i < E4; i += CSRG * CSRT) {
        if (!is64) {
            int4 d = ((const int4*)ei)[E4 + i];
            atomicAdd(&g_cc[d.x], 1); atomicAdd(&g_cc[d.y], 1);
            atomicAdd(&g_cc[d.z], 1); atomicAdd(&g_cc[d.w], 1);
        } else {
            const long long* p = (const long long*)ei;
#pragma unroll
            for (int j = 0; j < 4; j++) atomicAdd(&g_cc[(int)p[EE + 4 * i + j]], 1);
        }
    }
    gsync(CSRG);

    // Phase B: per-1024-node exclusive scan (blocks 0..NB-1; 4 nodes/thread)
    if (bid < NB) {
        int base = bid * 1024 + tid * 4;
        int c0 = 0, c1 = 0, c2 = 0, c3 = 0;
        if (base + 0 < NN) c0 = g_cc[base + 0];
        if (base + 1 < NN) c1 = g_cc[base + 1];
        if (base + 2 < NN) c2 = g_cc[base + 2];
        if (base + 3 < NN) c3 = g_cc[base + 3];
        int v = c0 + c1 + c2 + c3;
        s_scan[tid] = v;
        __syncthreads();
        for (int off = 1; off < CSRT; off <<= 1) {
            int t2 = (tid >= off) ? s_scan[tid - off] : 0;
            __syncthreads();
            s_scan[tid] += t2;
            __syncthreads();
        }
        int incl = s_scan[tid];
        int excl = incl - v;
        if (base + 0 < NN) g_rowptr[base + 0] = excl;
        if (base + 1 < NN) g_rowptr[base + 1] = excl + c0;
        if (base + 2 < NN) g_rowptr[base + 2] = excl + c0 + c1;
        if (base + 3 < NN) g_rowptr[base + 3] = excl + c0 + c1 + c2;
        if (tid == CSRT - 1) g_bsum[bid] = incl;
    }
    gsync(2 * CSRG);

    // Phase C: block 0 exclusive-scans the NB block sums
    if (bid == 0) {
        int lane = tid & 31, w = tid >> 5;
        int v = (tid < NB) ? g_bsum[tid] : 0;
        int x = v;
#pragma unroll
        for (int off = 1; off < 32; off <<= 1) {
            int y = __shfl_up_sync(0xffffffffu, x, off);
            if (lane >= off) x += y;
        }
        if (lane == 31 && w < 4) s_scan[w] = x;
        __syncthreads();
        if (tid < NB) {
            int woff = 0;
#pragma unroll
            for (int q = 0; q < 4; q++) if (q < w) woff += s_scan[q];
            g_bsum[tid] = x - v + woff;
        }
    }
    gsync(3 * CSRG);

    // Phase D: fill edge records
    for (int i = bid * CSRT + tid; i < E4; i += CSRG * CSRT) {
        if (!is64) {
            int4 s4 = ((const int4*)ei)[i];
            int4 d4 = ((const int4*)ei)[E4 + i];
            fill_one(s4.x, d4.x); fill_one(s4.y, d4.y);
            fill_one(s4.z, d4.z); fill_one(s4.w, d4.w);
        } else {
            const long long* p = (const long long*)ei;
#pragma unroll
            for (int j = 0; j < 4; j++)
                fill_one((int)p[4 * i + j], (int)p[EE + 4 * i + j]);
        }
    }
}

// ---------------- GEMM fp32 -> fp16 rows (no bias/relu; conv path) ----------------
__global__ __launch_bounds__(256)
void k_gemmH(const float* __restrict__ in, const float* __restrict__ W,
             __half2* __restrict__ out, int row0) {
    __shared__ __align__(16) float Ws[CC * CC];
    int tid = threadIdx.x;
    for (int idx = tid; idx < CC * CC; idx += 256) Ws[idx] = W[idx];
    __syncthreads();

    int row = row0 + blockIdx.x * 256 + tid;
    if (row >= NN) return;

    float x[CC];
    const float4* xr = (const float4*)(in + (size_t)row * CC);
#pragma unroll
    for (int j = 0; j < CC / 4; j++) {
        float4 t = xr[j];
        x[4 * j] = t.x; x[4 * j + 1] = t.y; x[4 * j + 2] = t.z; x[4 * j + 3] = t.w;
    }

#pragma unroll
    for (int c = 0; c < 4; c++) {           // 4 chunks of 16 cols
        ull acc[8];
#pragma unroll
        for (int j = 0; j < 8; j++) acc[j] = 0ull;
#pragma unroll
        for (int k = 0; k < CC; k++) {
            ull x2 = pack2(x[k]);
            const ulonglong2* w2 = (const ulonglong2*)(Ws + k * CC + c * 16);
#pragma unroll
            for (int j = 0; j < 4; j++) {
                ulonglong2 w = w2[j];
                fma2(acc[2 * j],     x2, w.x);
                fma2(acc[2 * j + 1], x2, w.y);
            }
        }
        __half2 h[8];
#pragma unroll
        for (int j = 0; j < 8; j++) {
            float lo, hi;
            unpack2(acc[j], lo, hi);
            h[j] = __floats2half2_rn(lo, hi);
        }
        uint4 o0, o1;
        o0.x = *(unsigned*)&h[0]; o0.y = *(unsigned*)&h[1];
        o0.z = *(unsigned*)&h[2]; o0.w = *(unsigned*)&h[3];
        o1.x = *(unsigned*)&h[4]; o1.y = *(unsigned*)&h[5];
        o1.z = *(unsigned*)&h[6]; o1.w = *(unsigned*)&h[7];
        uint4* dst = (uint4*)(out + (size_t)row * 32 + c * 8);
        dst[0] = o0; dst[1] = o1;
    }
}

// ---------------- GEMM fp32 -> fp32 (+bias)(relu); MLP path ----------------
template <int OUTF, int CHUNK, bool RELU>
__global__ __launch_bounds__(256)
void k_gemmF(const float* __restrict__ in, const float* __restrict__ W,
             const float* __restrict__ bias, float* __restrict__ out) {
    __shared__ __align__(16) float Ws[CC * OUTF];
    int tid = threadIdx.x;
    for (int idx = tid; idx < CC * OUTF; idx += 256) Ws[idx] = W[idx];
    __syncthreads();

    int row = blockIdx.x * 256 + tid;
    if (row >= NN) return;

    float x[CC];
    const float4* xr = (const float4*)(in + (size_t)row * CC);
#pragma unroll
    for (int j = 0; j < CC / 4; j++) {
        float4 t = xr[j];
        x[4 * j] = t.x; x[4 * j + 1] = t.y; x[4 * j + 2] = t.z; x[4 * j + 3] = t.w;
    }

#pragma unroll
    for (int c = 0; c < OUTF / CHUNK; c++) {
        ull acc[CHUNK / 2];
#pragma unroll
        for (int j = 0; j < CHUNK / 2; j++) acc[j] = 0ull;
#pragma unroll
        for (int k = 0; k < CC; k++) {
            ull x2 = pack2(x[k]);
            const ulonglong2* w2 = (const ulonglong2*)(Ws + k * OUTF + c * CHUNK);
#pragma unroll
            for (int j = 0; j < CHUNK / 4; j++) {
                ulonglong2 w = w2[j];
                fma2(acc[2 * j],     x2, w.x);
                fma2(acc[2 * j + 1], x2, w.y);
            }
        }
        float* o = out + (size_t)row * OUTF + c * CHUNK;
#pragma unroll
        for (int j = 0; j < CHUNK / 2; j++) {
            float lo, hi;
            unpack2(acc[j], lo, hi);
            lo += __ldg(&bias[c * CHUNK + 2 * j]);
            hi += __ldg(&bias[c * CHUNK + 2 * j + 1]);
            if (RELU) { lo = fmaxf(lo, 0.f); hi = fmaxf(hi, 0.f); }
            o[2 * j] = lo; o[2 * j + 1] = hi;
        }
    }
}

// ---------------- aggregation: warp/node, fp16 rows, one LDG.32/lane per edge ----------------
template <bool RELU>
__global__ __launch_bounds__(256)
void k_agg(const __half2* __restrict__ hf, const float* __restrict__ bias,
           float* __restrict__ out) {
    int node = blockIdx.x * 8 + (threadIdx.x >> 5);
    int lane = threadIdx.x & 31;

    int deg = g_cc[node];
    float self = __frcp_rn((float)deg + 1.0f);   // dinv^2
    float2 acc;
    {
        float2 v = __half22float2(hf[(size_t)node * 32 + lane]);
        acc.x = v.x * self; acc.y = v.y * self;
    }

    int beg = g_rowptr[node] + g_bsum[node >> 10];
    int end = (node + 1 == NN) ? EE : (g_rowptr[node + 1] + g_bsum[(node + 1) >> 10]);

    int e = beg;
    for (; e + 3 < end; e += 4) {
        int2 m0 = g_edge[e],     m1 = g_edge[e + 1];
        int2 m2 = g_edge[e + 2], m3 = g_edge[e + 3];
        float2 v0 = __half22float2(hf[(size_t)m0.x * 32 + lane]);
        float2 v1 = __half22float2(hf[(size_t)m1.x * 32 + lane]);
        float2 v2 = __half22float2(hf[(size_t)m2.x * 32 + lane]);
        float2 v3 = __half22float2(hf[(size_t)m3.x * 32 + lane]);
        float n0 = __int_as_float(m0.y), n1 = __int_as_float(m1.y);
        float n2 = __int_as_float(m2.y), n3 = __int_as_float(m3.y);
        acc.x = fmaf(v0.x, n0, acc.x); acc.y = fmaf(v0.y, n0, acc.y);
        acc.x = fmaf(v1.x, n1, acc.x); acc.y = fmaf(v1.y, n1, acc.y);
        acc.x = fmaf(v2.x, n2, acc.x); acc.y = fmaf(v2.y, n2, acc.y);
        acc.x = fmaf(v3.x, n3, acc.x); acc.y = fmaf(v3.y, n3, acc.y);
    }
    for (; e < end; e++) {
        int2 m = g_edge[e];
        float2 v = __half22float2(hf[(size_t)m.x * 32 + lane]);
        float nm = __int_as_float(m.y);
        acc.x = fmaf(v.x, nm, acc.x); acc.y = fmaf(v.y, nm, acc.y);
    }

    float2 bv = ((const float2*)bias)[lane];
    acc.x += bv.x; acc.y += bv.y;
    if (RELU) { acc.x = fmaxf(acc.x, 0.f); acc.y = fmaxf(acc.y, 0.f); }
    ((float2*)(out + (size_t)node * CC))[lane] = acc;
}

// ---------------- launcher ----------------
extern "C" void kernel_launch(void* const* d_in, const int* in_sizes, int n_in,
                              void* d_out, int out_size) {
    const float* x   = (const float*)d_in[0];
    const void*  ei  = d_in[1];
    const float* W1  = (const float*)d_in[2];
    const float* b1  = (const float*)d_in[3];
    const float* W2  = (const float*)d_in[4];
    const float* b2  = (const float*)d_in[5];
    const float* Wm1 = (const float*)d_in[6];
    const float* bm1 = (const float*)d_in[7];
    const float* Wm2 = (const float*)d_in[8];
    const float* bm2 = (const float*)d_in[9];
    float* out = (float*)d_out;

    void *pcc = nullptr, *phf = nullptr, *ph2 = nullptr;
    cudaGetSymbolAddress(&pcc, g_cc);
    cudaGetSymbolAddress(&phf, g_hf);
    cudaGetSymbolAddress(&ph2, g_h2);
    __half2* hf = (__half2*)phf;
    float*   h2 = (float*)ph2;

    cudaMemsetAsync(pcc, 0, (2 * NN + 4) * sizeof(int));

    // launch order puts agg1 in the ncu-profiled slot (4th kernel)
    k_gemmH<<<196, 256>>>(x, W1, hf, 0);          // 1: rows [0, 50176)
    k_gemmH<<<195, 256>>>(x, W1, hf, 50176);      // 2: rows [50176, NN)
    k_csr  <<<CSRG, CSRT>>>(ei);                  // 3: hist+scan+fill fused
    k_agg<true><<<NN / 8, 256>>>(hf, b1, h2);     // 4: conv1 agg (PROFILED)
    k_gemmH<<<391, 256>>>(h2, W2, hf, 0);         // 5
    k_agg<false><<<NN / 8, 256>>>(hf, b2, h2);    // 6: conv2 agg
    k_gemmF<64, 16, true ><<<391, 256>>>(h2, Wm1, bm1, h2);   // 7: MLP1 (in-place)
    k_gemmF<40, 20, false><<<391, 256>>>(h2, Wm2, bm2, out);  // 8: MLP2
}

// round 9
// speedup vs baseline: 1.4133x; 1.0575x over previous
#include <cuda_runtime.h>
#include <cuda_fp16.h>

#define NN 100000
#define EE 1000000
#define CC 64
#define OUTC 40
#define NB 98          // ceil(NN/1024)
#define E4 (EE/4)
#define CSRG 592       // resident grid: 148 SMs x 8 blocks guaranteed by launch_bounds
#define CSRT 256

typedef unsigned long long ull;

// ---------------- device scratch ----------------
__device__ int     g_cc[2 * NN + 4];   // [0,NN) counts ; [NN,2NN) cursors ; [2NN] barrier
__device__ int     g_rowptr[NN];
__device__ int     g_bsum[NB];
__device__ int2    g_edge[EE];         // {src*8 (uint4 idx), bitcast(norm)} grouped by dst
__device__ __half2 g_hf[NN * CC / 2];  // fp16 feature rows (gather input)
__device__ float   g_h2[NN * CC];      // fp32 feature rows

// ---------------- f32x2 helpers ----------------
__device__ __forceinline__ ull pack2(float v) {
    ull r; asm("mov.b64 %0, {%1, %1};" : "=l"(r) : "f"(v)); return r;
}
__device__ __forceinline__ void fma2(ull& d, ull a, ull b) {
    asm("fma.rn.f32x2 %0, %1, %2, %0;" : "+l"(d) : "l"(a), "l"(b));
}
__device__ __forceinline__ void unpack2(ull v, float& lo, float& hi) {
    asm("mov.b64 {%0, %1}, %2;" : "=f"(lo), "=f"(hi) : "l"(v));
}

// ---------------- fused CSR build: hist -> scan -> fill, one kernel ----------------
__device__ __forceinline__ void gsync(int target) {
    __threadfence();
    __syncthreads();
    if (threadIdx.x == 0) {
        atomicAdd(&g_cc[2 * NN], 1);
        while (atomicAdd(&g_cc[2 * NN], 0) < target) __nanosleep(64);
        __threadfence();
    }
    __syncthreads();
}

__device__ __forceinline__ void fill_one(int s, int d) {
    float ns = rsqrtf((float)g_cc[s] + 1.0f);
    float nd = rsqrtf((float)g_cc[d] + 1.0f);
    int pos = g_rowptr[d] + g_bsum[d >> 10] + atomicAdd(&g_cc[NN + d], 1);
    g_edge[pos] = make_int2(s * 8, __float_as_int(ns * nd));
}

__global__ __launch_bounds__(CSRT, 8)
void k_csr(const void* __restrict__ ei) {
    __shared__ int s_is64;
    __shared__ int s_scan[CSRT];
    int tid = threadIdx.x, bid = blockIdx.x;

    if (tid == 0) {
        const long long* p = (const long long*)ei;
        int ok = 1;
#pragma unroll
        for (int i = 0; i < 16; i++) { long long v = p[i]; if (v < 0 || v >= NN) ok = 0; }
        s_is64 = ok;
    }
    __syncthreads();
    int is64 = s_is64;

    // Phase A: degree histogram
    for (int i = bid * CSRT + tid; i < E4; i += CSRG * CSRT) {
        if (!is64) {
            int4 d = ((const int4*)ei)[E4 + i];
            atomicAdd(&g_cc[d.x], 1); atomicAdd(&g_cc[d.y], 1);
            atomicAdd(&g_cc[d.z], 1); atomicAdd(&g_cc[d.w], 1);
        } else {
            const long long* p = (const long long*)ei;
#pragma unroll
            for (int j = 0; j < 4; j++) atomicAdd(&g_cc[(int)p[EE + 4 * i + j]], 1);
        }
    }
    gsync(CSRG);

    // Phase B: per-1024-node exclusive scan (blocks 0..NB-1; 4 nodes/thread)
    if (bid < NB) {
        int base = bid * 1024 + tid * 4;
        int c0 = 0, c1 = 0, c2 = 0, c3 = 0;
        if (base + 0 < NN) c0 = g_cc[base + 0];
        if (base + 1 < NN) c1 = g_cc[base + 1];
        if (base + 2 < NN) c2 = g_cc[base + 2];
        if (base + 3 < NN) c3 = g_cc[base + 3];
        int v = c0 + c1 + c2 + c3;
        s_scan[tid] = v;
        __syncthreads();
        for (int off = 1; off < CSRT; off <<= 1) {
            int t2 = (tid >= off) ? s_scan[tid - off] : 0;
            __syncthreads();
            s_scan[tid] += t2;
            __syncthreads();
        }
        int incl = s_scan[tid];
        int excl = incl - v;
        if (base + 0 < NN) g_rowptr[base + 0] = excl;
        if (base + 1 < NN) g_rowptr[base + 1] = excl + c0;
        if (base + 2 < NN) g_rowptr[base + 2] = excl + c0 + c1;
        if (base + 3 < NN) g_rowptr[base + 3] = excl + c0 + c1 + c2;
        if (tid == CSRT - 1) g_bsum[bid] = incl;
    }
    gsync(2 * CSRG);

    // Phase C: block 0 exclusive-scans the NB block sums
    if (bid == 0) {
        int lane = tid & 31, w = tid >> 5;
        int v = (tid < NB) ? g_bsum[tid] : 0;
        int x = v;
#pragma unroll
        for (int off = 1; off < 32; off <<= 1) {
            int y = __shfl_up_sync(0xffffffffu, x, off);
            if (lane >= off) x += y;
        }
        if (lane == 31 && w < 4) s_scan[w] = x;
        __syncthreads();
        if (tid < NB) {
            int woff = 0;
#pragma unroll
            for (int q = 0; q < 4; q++) if (q < w) woff += s_scan[q];
            g_bsum[tid] = x - v + woff;
        }
    }
    gsync(3 * CSRG);

    // Phase D: fill edge records
    for (int i = bid * CSRT + tid; i < E4; i += CSRG * CSRT) {
        if (!is64) {
            int4 s4 = ((const int4*)ei)[i];
            int4 d4 = ((const int4*)ei)[E4 + i];
            fill_one(s4.x, d4.x); fill_one(s4.y, d4.y);
            fill_one(s4.z, d4.z); fill_one(s4.w, d4.w);
        } else {
            const long long* p = (const long long*)ei;
#pragma unroll
            for (int j = 0; j < 4; j++)
                fill_one((int)p[4 * i + j], (int)p[EE + 4 * i + j]);
        }
    }
}

// ---------------- GEMM fp32 -> fp16 rows (no bias/relu; conv path) ----------------
__global__ __launch_bounds__(256)
void k_gemmH(const float* __restrict__ in, const float* __restrict__ W,
             __half2* __restrict__ out) {
    __shared__ __align__(16) float Ws[CC * CC];
    int tid = threadIdx.x;
    for (int idx = tid; idx < CC * CC; idx += 256) Ws[idx] = W[idx];
    __syncthreads();

    int row = blockIdx.x * 256 + tid;
    if (row >= NN) return;

    float x[CC];
    const float4* xr = (const float4*)(in + (size_t)row * CC);
#pragma unroll
    for (int j = 0; j < CC / 4; j++) {
        float4 t = xr[j];
        x[4 * j] = t.x; x[4 * j + 1] = t.y; x[4 * j + 2] = t.z; x[4 * j + 3] = t.w;
    }

#pragma unroll
    for (int c = 0; c < 4; c++) {           // 4 chunks of 16 cols
        ull acc[8];
#pragma unroll
        for (int j = 0; j < 8; j++) acc[j] = 0ull;
#pragma unroll
        for (int k = 0; k < CC; k++) {
            ull x2 = pack2(x[k]);
            const ulonglong2* w2 = (const ulonglong2*)(Ws + k * CC + c * 16);
#pragma unroll
            for (int j = 0; j < 4; j++) {
                ulonglong2 w = w2[j];
                fma2(acc[2 * j],     x2, w.x);
                fma2(acc[2 * j + 1], x2, w.y);
            }
        }
        __half2 h[8];
#pragma unroll
        for (int j = 0; j < 8; j++) {
            float lo, hi;
            unpack2(acc[j], lo, hi);
            h[j] = __floats2half2_rn(lo, hi);
        }
        uint4 o0, o1;
        o0.x = *(unsigned*)&h[0]; o0.y = *(unsigned*)&h[1];
        o0.z = *(unsigned*)&h[2]; o0.w = *(unsigned*)&h[3];
        o1.x = *(unsigned*)&h[4]; o1.y = *(unsigned*)&h[5];
        o1.z = *(unsigned*)&h[6]; o1.w = *(unsigned*)&h[7];
        uint4* dst = (uint4*)(out + (size_t)row * 32 + c * 8);
        dst[0] = o0; dst[1] = o1;
    }
}

// ---------------- GEMM fp32 -> fp32 (+bias)(relu); MLP path ----------------
template <int OUTF, int CHUNK, bool RELU>
__global__ __launch_bounds__(256)
void k_gemmF(const float* __restrict__ in, const float* __restrict__ W,
             const float* __restrict__ bias, float* __restrict__ out) {
    __shared__ __align__(16) float Ws[CC * OUTF];
    int tid = threadIdx.x;
    for (int idx = tid; idx < CC * OUTF; idx += 256) Ws[idx] = W[idx];
    __syncthreads();

    int row = blockIdx.x * 256 + tid;
    if (row >= NN) return;

    float x[CC];
    const float4* xr = (const float4*)(in + (size_t)row * CC);
#pragma unroll
    for (int j = 0; j < CC / 4; j++) {
        float4 t = xr[j];
        x[4 * j] = t.x; x[4 * j + 1] = t.y; x[4 * j + 2] = t.z; x[4 * j + 3] = t.w;
    }

#pragma unroll
    for (int c = 0; c < OUTF / CHUNK; c++) {
        ull acc[CHUNK / 2];
#pragma unroll
        for (int j = 0; j < CHUNK / 2; j++) acc[j] = 0ull;
#pragma unroll
        for (int k = 0; k < CC; k++) {
            ull x2 = pack2(x[k]);
            const ulonglong2* w2 = (const ulonglong2*)(Ws + k * OUTF + c * CHUNK);
#pragma unroll
            for (int j = 0; j < CHUNK / 4; j++) {
                ulonglong2 w = w2[j];
                fma2(acc[2 * j],     x2, w.x);
                fma2(acc[2 * j + 1], x2, w.y);
            }
        }
        float* o = out + (size_t)row * OUTF + c * CHUNK;
#pragma unroll
        for (int j = 0; j < CHUNK / 2; j++) {
            float lo, hi;
            unpack2(acc[j], lo, hi);
            lo += __ldg(&bias[c * CHUNK + 2 * j]);
            hi += __ldg(&bias[c * CHUNK + 2 * j + 1]);
            if (RELU) { lo = fmaxf(lo, 0.f); hi = fmaxf(hi, 0.f); }
            o[2 * j] = lo; o[2 * j + 1] = hi;
        }
    }
}

// ---------------- aggregation: 4 nodes/warp, 8 lanes/node, LDG.128 gathers ----------------
template <bool RELU>
__global__ __launch_bounds__(256)
void k_agg(const __half2* __restrict__ hf, const float* __restrict__ bias,
           float* __restrict__ out) {
    const uint4* hf4 = (const uint4*)hf;          // one uint4 = 8 halfs = 1/8 row
    int node = blockIdx.x * 32 + ((threadIdx.x >> 3));   // 4 nodes per warp, 32 per block
    int l = threadIdx.x & 7;                      // lane within node-group

    int deg = g_cc[node];
    float self = __frcp_rn((float)deg + 1.0f);    // dinv^2

    float a0, a1, a2, a3, a4, a5, a6, a7;
    {
        uint4 v = hf4[node * 8 + l];
        const __half2* hp = (const __half2*)&v;
        float2 f0 = __half22float2(hp[0]), f1 = __half22float2(hp[1]);
        float2 f2 = __half22float2(hp[2]), f3 = __half22float2(hp[3]);
        a0 = f0.x * self; a1 = f0.y * self;
        a2 = f1.x * self; a3 = f1.y * self;
        a4 = f2.x * self; a5 = f2.y * self;
        a6 = f3.x * self; a7 = f3.y * self;
    }

    int beg = g_rowptr[node] + g_bsum[node >> 10];
    int end = (node + 1 == NN) ? EE : (g_rowptr[node + 1] + g_bsum[(node + 1) >> 10]);

    int e = beg;
    for (; e + 1 < end; e += 2) {
        int2 m0 = g_edge[e], m1 = g_edge[e + 1];
        uint4 v0 = hf4[m0.x + l];
        uint4 v1 = hf4[m1.x + l];
        float n0 = __int_as_float(m0.y);
        float n1 = __int_as_float(m1.y);
        {
            const __half2* hp = (const __half2*)&v0;
            float2 f0 = __half22float2(hp[0]), f1 = __half22float2(hp[1]);
            float2 f2 = __half22float2(hp[2]), f3 = __half22float2(hp[3]);
            a0 = fmaf(f0.x, n0, a0); a1 = fmaf(f0.y, n0, a1);
            a2 = fmaf(f1.x, n0, a2); a3 = fmaf(f1.y, n0, a3);
            a4 = fmaf(f2.x, n0, a4); a5 = fmaf(f2.y, n0, a5);
            a6 = fmaf(f3.x, n0, a6); a7 = fmaf(f3.y, n0, a7);
        }
        {
            const __half2* hp = (const __half2*)&v1;
            float2 f0 = __half22float2(hp[0]), f1 = __half22float2(hp[1]);
            float2 f2 = __half22float2(hp[2]), f3 = __half22float2(hp[3]);
            a0 = fmaf(f0.x, n1, a0); a1 = fmaf(f0.y, n1, a1);
            a2 = fmaf(f1.x, n1, a2); a3 = fmaf(f1.y, n1, a3);
            a4 = fmaf(f2.x, n1, a4); a5 = fmaf(f2.y, n1, a5);
            a6 = fmaf(f3.x, n1, a6); a7 = fmaf(f3.y, n1, a7);
        }
    }
    if (e < end) {
        int2 m = g_edge[e];
        uint4 v = hf4[m.x + l];
        float nm = __int_as_float(m.y);
        const __half2* hp = (const __half2*)&v;
        float2 f0 = __half22float2(hp[0]), f1 = __half22float2(hp[1]);
        float2 f2 = __half22float2(hp[2]), f3 = __half22float2(hp[3]);
        a0 = fmaf(f0.x, nm, a0); a1 = fmaf(f0.y, nm, a1);
        a2 = fmaf(f1.x, nm, a2); a3 = fmaf(f1.y, nm, a3);
        a4 = fmaf(f2.x, nm, a4); a5 = fmaf(f2.y, nm, a5);
        a6 = fmaf(f3.x, nm, a6); a7 = fmaf(f3.y, nm, a7);
    }

    const float4* b4 = (const float4*)(bias + l * 8);
    float4 bA = b4[0], bB = b4[1];
    a0 += bA.x; a1 += bA.y; a2 += bA.z; a3 += bA.w;
    a4 += bB.x; a5 += bB.y; a6 += bB.z; a7 += bB.w;
    if (RELU) {
        a0 = fmaxf(a0, 0.f); a1 = fmaxf(a1, 0.f);
        a2 = fmaxf(a2, 0.f); a3 = fmaxf(a3, 0.f);
        a4 = fmaxf(a4, 0.f); a5 = fmaxf(a5, 0.f);
        a6 = fmaxf(a6, 0.f); a7 = fmaxf(a7, 0.f);
    }
    float4* o = (float4*)(out + (size_t)node * CC + l * 8);
    o[0] = make_float4(a0, a1, a2, a3);
    o[1] = make_float4(a4, a5, a6, a7);
}

// ---------------- launcher ----------------
extern "C" void kernel_launch(void* const* d_in, const int* in_sizes, int n_in,
                              void* d_out, int out_size) {
    const float* x   = (const float*)d_in[0];
    const void*  ei  = d_in[1];
    const float* W1  = (const float*)d_in[2];
    const float* b1  = (const float*)d_in[3];
    const float* W2  = (const float*)d_in[4];
    const float* b2  = (const float*)d_in[5];
    const float* Wm1 = (const float*)d_in[6];
    const float* bm1 = (const float*)d_in[7];
    const float* Wm2 = (const float*)d_in[8];
    const float* bm2 = (const float*)d_in[9];
    float* out = (float*)d_out;

    void *pcc = nullptr, *phf = nullptr, *ph2 = nullptr;
    cudaGetSymbolAddress(&pcc, g_cc);
    cudaGetSymbolAddress(&phf, g_hf);
    cudaGetSymbolAddress(&ph2, g_h2);
    __half2* hf = (__half2*)phf;
    float*   h2 = (float*)ph2;

    cudaMemsetAsync(pcc, 0, (2 * NN + 4) * sizeof(int));

    // ncu captures the 4th kernel launch -> k_gemmH(h2, W2) this round
    k_csr  <<<CSRG, CSRT>>>(ei);                  // 1
    k_gemmH<<<391, 256>>>(x, W1, hf);             // 2
    k_agg<true><<<3125, 256>>>(hf, b1, h2);       // 3: conv1 agg
    k_gemmH<<<391, 256>>>(h2, W2, hf);            // 4: PROFILED
    k_agg<false><<<3125, 256>>>(hf, b2, h2);      // 5: conv2 agg
    k_gemmF<64, 16, true ><<<391, 256>>>(h2, Wm1, bm1, h2);   // 6: MLP1 (in-place)
    k_gemmF<40, 20, false><<<391, 256>>>(h2, Wm2, bm2, out);  // 7: MLP2
}

// round 11
// speedup vs baseline: 2.7852x; 1.9708x over previous
#include <cuda_runtime.h>
#include <cuda_fp16.h>

#define NN 100000
#define EE 1000000
#define CC 64
#define OUTC 40
#define NB 98          // ceil(NN/1024)
#define E4 (EE/4)
#define CSRG 592       // resident grid: 148 SMs x 8 blocks guaranteed by launch_bounds
#define CSRT 256
#define NTILES 6250    // NN/16
#define GEMMG 250      // gemm grid (2000 warps)

typedef unsigned long long ull;

// ---------------- device scratch ----------------
__device__ int     g_cc[2 * NN + 4];   // [0,NN) counts ; [NN,2NN) cursors ; [2NN] barrier
__device__ int     g_rowptr[NN];
__device__ int     g_bsum[NB];
__device__ int2    g_edge[EE];         // {src*8 (uint4 idx), bitcast(norm)} grouped by dst
__device__ __half2 g_bufA[NN * CC / 2];
__device__ __half2 g_bufB[NN * CC / 2];
__device__ __half  g_Wt1[CC * CC];     // transposed fp16 weights [n][k]
__device__ __half  g_Wt2[CC * CC];
__device__ __half  g_Wtm1[CC * CC];
__device__ __half  g_Wtm2[OUTC * CC];

// ---------------- weight prep: transpose + fp32->fp16 ----------------
__global__ void k_prep(const float* __restrict__ W1, const float* __restrict__ W2,
                       const float* __restrict__ Wm1, const float* __restrict__ Wm2) {
    int tid = threadIdx.x;
    for (int i = tid; i < CC * CC; i += 1024) {
        int n = i >> 6, k = i & 63;            // i = n*64+k
        g_Wt1[i]  = __float2half(W1[k * CC + n]);
        g_Wt2[i]  = __float2half(W2[k * CC + n]);
        g_Wtm1[i] = __float2half(Wm1[k * CC + n]);
    }
    for (int i = tid; i < OUTC * CC; i += 1024) {
        int n = i >> 6, k = i & 63;
        g_Wtm2[i] = __float2half(Wm2[k * OUTC + n]);
    }
}

// ---------------- x fp32 -> fp16 rows ----------------
__global__ __launch_bounds__(256)
void k_cvtx(const float* __restrict__ x, __half2* __restrict__ out) {
    int i = blockIdx.x * 256 + threadIdx.x;   // one uint4 (8 halfs) per thread
    if (i >= NN * 8) return;
    const float4* x4 = (const float4*)x;
    float4 f0 = x4[2 * i], f1 = x4[2 * i + 1];
    __half2 h0 = __floats2half2_rn(f0.x, f0.y);
    __half2 h1 = __floats2half2_rn(f0.z, f0.w);
    __half2 h2 = __floats2half2_rn(f1.x, f1.y);
    __half2 h3 = __floats2half2_rn(f1.z, f1.w);
    uint4 o;
    o.x = *(unsigned*)&h0; o.y = *(unsigned*)&h1;
    o.z = *(unsigned*)&h2; o.w = *(unsigned*)&h3;
    ((uint4*)out)[i] = o;
}

// ---------------- fused CSR build: hist -> scan -> fill, one kernel ----------------
__device__ __forceinline__ void gsync(int target) {
    __threadfence();
    __syncthreads();
    if (threadIdx.x == 0) {
        atomicAdd(&g_cc[2 * NN], 1);
        while (atomicAdd(&g_cc[2 * NN], 0) < target) __nanosleep(64);
        __threadfence();
    }
    __syncthreads();
}

__device__ __forceinline__ void fill_one(int s, int d) {
    float ns = rsqrtf((float)g_cc[s] + 1.0f);
    float nd = rsqrtf((float)g_cc[d] + 1.0f);
    int pos = g_rowptr[d] + g_bsum[d >> 10] + atomicAdd(&g_cc[NN + d], 1);
    g_edge[pos] = make_int2(s * 8, __float_as_int(ns * nd));
}

__global__ __launch_bounds__(CSRT, 8)
void k_csr(const void* __restrict__ ei) {
    __shared__ int s_is64;
    __shared__ int s_scan[CSRT];
    int tid = threadIdx.x, bid = blockIdx.x;

    if (tid == 0) {
        const long long* p = (const long long*)ei;
        int ok = 1;
#pragma unroll
        for (int i = 0; i < 16; i++) { long long v = p[i]; if (v < 0 || v >= NN) ok = 0; }
        s_is64 = ok;
    }
    __syncthreads();
    int is64 = s_is64;

    // Phase A: degree histogram
    for (int i = bid * CSRT + tid; i < E4; i += CSRG * CSRT) {
        if (!is64) {
            int4 d = ((const int4*)ei)[E4 + i];
            atomicAdd(&g_cc[d.x], 1); atomicAdd(&g_cc[d.y], 1);
            atomicAdd(&g_cc[d.z], 1); atomicAdd(&g_cc[d.w], 1);
        } else {
            const long long* p = (const long long*)ei;
#pragma unroll
            for (int j = 0; j < 4; j++) atomicAdd(&g_cc[(int)p[EE + 4 * i + j]], 1);
        }
    }
    gsync(CSRG);

    // Phase B: per-1024-node exclusive scan (blocks 0..NB-1; 4 nodes/thread)
    if (bid < NB) {
        int base = bid * 1024 + tid * 4;
        int c0 = 0, c1 = 0, c2 = 0, c3 = 0;
        if (base + 0 < NN) c0 = g_cc[base + 0];
        if (base + 1 < NN) c1 = g_cc[base + 1];
        if (base + 2 < NN) c2 = g_cc[base + 2];
        if (base + 3 < NN) c3 = g_cc[base + 3];
        int v = c0 + c1 + c2 + c3;
        s_scan[tid] = v;
        __syncthreads();
        for (int off = 1; off < CSRT; off <<= 1) {
            int t2 = (tid >= off) ? s_scan[tid - off] : 0;
            __syncthreads();
            s_scan[tid] += t2;
            __syncthreads();
        }
        int incl = s_scan[tid];
        int excl = incl - v;
        if (base + 0 < NN) g_rowptr[base + 0] = excl;
        if (base + 1 < NN) g_rowptr[base + 1] = excl + c0;
        if (base + 2 < NN) g_rowptr[base + 2] = excl + c0 + c1;
        if (base + 3 < NN) g_rowptr[base + 3] = excl + c0 + c1 + c2;
        if (tid == CSRT - 1) g_bsum[bid] = incl;
    }
    gsync(2 * CSRG);

    // Phase C: block 0 exclusive-scans the NB block sums
    if (bid == 0) {
        int lane = tid & 31, w = tid >> 5;
        int v = (tid < NB) ? g_bsum[tid] : 0;
        int x = v;
#pragma unroll
        for (int off = 1; off < 32; off <<= 1) {
            int y = __shfl_up_sync(0xffffffffu, x, off);
            if (lane >= off) x += y;
        }
        if (lane == 31 && w < 4) s_scan[w] = x;
        __syncthreads();
        if (tid < NB) {
            int woff = 0;
#pragma unroll
            for (int q = 0; q < 4; q++) if (q < w) woff += s_scan[q];
            g_bsum[tid] = x - v + woff;
        }
    }
    gsync(3 * CSRG);

    // Phase D: fill edge records
    for (int i = bid * CSRT + tid; i < E4; i += CSRG * CSRT) {
        if (!is64) {
            int4 s4 = ((const int4*)ei)[i];
            int4 d4 = ((const int4*)ei)[E4 + i];
            fill_one(s4.x, d4.x); fill_one(s4.y, d4.y);
            fill_one(s4.z, d4.z); fill_one(s4.w, d4.w);
        } else {
            const long long* p = (const long long*)ei;
#pragma unroll
            for (int j = 0; j < 4; j++)
                fill_one((int)p[4 * i + j], (int)p[EE + 4 * i + j]);
        }
    }
}

// ---------------- tensor-core GEMM: out[N, NT*8] = A[N,64](f16) @ Wt^T, f32 accum ----------------
__device__ __forceinline__ void mma16816(float c[4], unsigned a0, unsigned a1,
                                         unsigned a2, unsigned a3,
                                         unsigned b0, unsigned b1) {
    asm volatile(
        "mma.sync.aligned.m16n8k16.row.col.f32.f16.f16.f32 "
        "{%0,%1,%2,%3},{%4,%5,%6,%7},{%8,%9},{%0,%1,%2,%3};"
        : "+f"(c[0]), "+f"(c[1]), "+f"(c[2]), "+f"(c[3])
        : "r"(a0), "r"(a1), "r"(a2), "r"(a3), "r"(b0), "r"(b1));
}

template <int NT, bool BIAS, bool RELU, bool OUTF32>
__global__ __launch_bounds__(256)
void k_gemmTC(const __half* __restrict__ A, const __half* __restrict__ Wt,
              const float* __restrict__ bias, void* __restrict__ outv) {
    const int NCOLS = NT * 8;
    int lane = threadIdx.x & 31;
    int wg = (blockIdx.x * 256 + threadIdx.x) >> 5;   // global warp id
    int g = lane >> 2, t = lane & 3;

    // B fragments: held in registers for the kernel's lifetime
    unsigned b[4][NT][2];
#pragma unroll
    for (int ks = 0; ks < 4; ks++)
#pragma unroll
        for (int nt = 0; nt < NT; nt++) {
            const __half* base = Wt + (nt * 8 + g) * CC + ks * 16 + 2 * t;
            b[ks][nt][0] = *(const unsigned*)(base);
            b[ks][nt][1] = *(const unsigned*)(base + 8);
        }

    for (int tile = wg; tile < NTILES; tile += GEMMG * 8) {
        int r0 = tile * 16 + g;
        const __half* aU = A + (size_t)r0 * CC + 2 * t;        // rows g
        const __half* aL = aU + 8 * CC;                         // rows g+8

        float c[NT][4];
#pragma unroll
        for (int nt = 0; nt < NT; nt++) { c[nt][0] = c[nt][1] = c[nt][2] = c[nt][3] = 0.f; }

#pragma unroll
        for (int ks = 0; ks < 4; ks++) {
            unsigned a0 = *(const unsigned*)(aU + ks * 16);
            unsigned a1 = *(const unsigned*)(aL + ks * 16);
            unsigned a2 = *(const unsigned*)(aU + ks * 16 + 8);
            unsigned a3 = *(const unsigned*)(aL + ks * 16 + 8);
#pragma unroll
            for (int nt = 0; nt < NT; nt++)
                mma16816(c[nt], a0, a1, a2, a3, b[ks][nt][0], b[ks][nt][1]);
        }

#pragma unroll
        for (int nt = 0; nt < NT; nt++) {
            int col = nt * 8 + 2 * t;
            float c0 = c[nt][0], c1 = c[nt][1], c2 = c[nt][2], c3 = c[nt][3];
            if (BIAS) {
                float bb0 = __ldg(bias + col), bb1 = __ldg(bias + col + 1);
                c0 += bb0; c1 += bb1; c2 += bb0; c3 += bb1;
            }
            if (RELU) {
                c0 = fmaxf(c0, 0.f); c1 = fmaxf(c1, 0.f);
                c2 = fmaxf(c2, 0.f); c3 = fmaxf(c3, 0.f);
            }
            if (OUTF32) {
                float* o = (float*)outv;
                *(float2*)(o + (size_t)r0 * NCOLS + col)       = make_float2(c0, c1);
                *(float2*)(o + (size_t)(r0 + 8) * NCOLS + col) = make_float2(c2, c3);
            } else {
                __half* o = (__half*)outv;
                *(__half2*)(o + (size_t)r0 * NCOLS + col)       = __floats2half2_rn(c0, c1);
                *(__half2*)(o + (size_t)(r0 + 8) * NCOLS + col) = __floats2half2_rn(c2, c3);
            }
        }
    }
}

// ---------------- aggregation: 4 nodes/warp, 8 lanes/node, fp16 in -> fp16 out ----------------
template <bool RELU>
__global__ __launch_bounds__(256)
void k_agg(const __half2* __restrict__ hf, const float* __restrict__ bias,
           __half2* __restrict__ out) {
    const uint4* hf4 = (const uint4*)hf;          // one uint4 = 8 halfs = 1/8 row
    int node = blockIdx.x * 32 + (threadIdx.x >> 3);
    int l = threadIdx.x & 7;

    int deg = g_cc[node];
    float self = __frcp_rn((float)deg + 1.0f);    // dinv^2

    float a0, a1, a2, a3, a4, a5, a6, a7;
    {
        uint4 v = hf4[node * 8 + l];
        const __half2* hp = (const __half2*)&v;
        float2 f0 = __half22float2(hp[0]), f1 = __half22float2(hp[1]);
        float2 f2 = __half22float2(hp[2]), f3 = __half22float2(hp[3]);
        a0 = f0.x * self; a1 = f0.y * self;
        a2 = f1.x * self; a3 = f1.y * self;
        a4 = f2.x * self; a5 = f2.y * self;
        a6 = f3.x * self; a7 = f3.y * self;
    }

    int beg = g_rowptr[node] + g_bsum[node >> 10];
    int end = (node + 1 == NN) ? EE : (g_rowptr[node + 1] + g_bsum[(node + 1) >> 10]);

    int e = beg;
    for (; e + 1 < end; e += 2) {
        int2 m0 = g_edge[e], m1 = g_edge[e + 1];
        uint4 v0 = hf4[m0.x + l];
        uint4 v1 = hf4[m1.x + l];
        float n0 = __int_as_float(m0.y);
        float n1 = __int_as_float(m1.y);
        {
            const __half2* hp = (const __half2*)&v0;
            float2 f0 = __half22float2(hp[0]), f1 = __half22float2(hp[1]);
            float2 f2 = __half22float2(hp[2]), f3 = __half22float2(hp[3]);
            a0 = fmaf(f0.x, n0, a0); a1 = fmaf(f0.y, n0, a1);
            a2 = fmaf(f1.x, n0, a2); a3 = fmaf(f1.y, n0, a3);
            a4 = fmaf(f2.x, n0, a4); a5 = fmaf(f2.y, n0, a5);
            a6 = fmaf(f3.x, n0, a6); a7 = fmaf(f3.y, n0, a7);
        }
        {
            const __half2* hp = (const __half2*)&v1;
            float2 f0 = __half22float2(hp[0]), f1 = __half22float2(hp[1]);
            float2 f2 = __half22float2(hp[2]), f3 = __half22float2(hp[3]);
            a0 = fmaf(f0.x, n1, a0); a1 = fmaf(f0.y, n1, a1);
            a2 = fmaf(f1.x, n1, a2); a3 = fmaf(f1.y, n1, a3);
            a4 = fmaf(f2.x, n1, a4); a5 = fmaf(f2.y, n1, a5);
            a6 = fmaf(f3.x, n1, a6); a7 = fmaf(f3.y, n1, a7);
        }
    }
    if (e < end) {
        int2 m = g_edge[e];
        uint4 v = hf4[m.x + l];
        float nm = __int_as_float(m.y);
        const __half2* hp = (const __half2*)&v;
        float2 f0 = __half22float2(hp[0]), f1 = __half22float2(hp[1]);
        float2 f2 = __half22float2(hp[2]), f3 = __half22float2(hp[3]);
        a0 = fmaf(f0.x, nm, a0); a1 = fmaf(f0.y, nm, a1);
        a2 = fmaf(f1.x, nm, a2); a3 = fmaf(f1.y, nm, a3);
        a4 = fmaf(f2.x, nm, a4); a5 = fmaf(f2.y, nm, a5);
        a6 = fmaf(f3.x, nm, a6); a7 = fmaf(f3.y, nm, a7);
    }

    const float4* b4 = (const float4*)(bias + l * 8);
    float4 bA = b4[0], bB = b4[1];
    a0 += bA.x; a1 += bA.y; a2 += bA.z; a3 += bA.w;
    a4 += bB.x; a5 += bB.y; a6 += bB.z; a7 += bB.w;
    if (RELU) {
        a0 = fmaxf(a0, 0.f); a1 = fmaxf(a1, 0.f);
        a2 = fmaxf(a2, 0.f); a3 = fmaxf(a3, 0.f);
        a4 = fmaxf(a4, 0.f); a5 = fmaxf(a5, 0.f);
        a6 = fmaxf(a6, 0.f); a7 = fmaxf(a7, 0.f);
    }
    __half2 h0 = __floats2half2_rn(a0, a1);
    __half2 h1 = __floats2half2_rn(a2, a3);
    __half2 h2 = __floats2half2_rn(a4, a5);
    __half2 h3 = __floats2half2_rn(a6, a7);
    uint4 o;
    o.x = *(unsigned*)&h0; o.y = *(unsigned*)&h1;
    o.z = *(unsigned*)&h2; o.w = *(unsigned*)&h3;
    ((uint4*)out)[node * 8 + l] = o;
}

// ---------------- launcher ----------------
extern "C" void kernel_launch(void* const* d_in, const int* in_sizes, int n_in,
                              void* d_out, int out_size) {
    const float* x   = (const float*)d_in[0];
    const void*  ei  = d_in[1];
    const float* W1  = (const float*)d_in[2];
    const float* b1  = (const float*)d_in[3];
    const float* W2  = (const float*)d_in[4];
    const float* b2  = (const float*)d_in[5];
    const float* Wm1 = (const float*)d_in[6];
    const float* bm1 = (const float*)d_in[7];
    const float* Wm2 = (const float*)d_in[8];
    const float* bm2 = (const float*)d_in[9];
    float* out = (float*)d_out;

    void *pcc = nullptr, *pa = nullptr, *pb = nullptr;
    void *pw1 = nullptr, *pw2 = nullptr, *pm1 = nullptr, *pm2 = nullptr;
    cudaGetSymbolAddress(&pcc, g_cc);
    cudaGetSymbolAddress(&pa, g_bufA);
    cudaGetSymbolAddress(&pb, g_bufB);
    cudaGetSymbolAddress(&pw1, g_Wt1);
    cudaGetSymbolAddress(&pw2, g_Wt2);
    cudaGetSymbolAddress(&pm1, g_Wtm1);
    cudaGetSymbolAddress(&pm2, g_Wtm2);
    __half2* bufA = (__half2*)pa;
    __half2* bufB = (__half2*)pb;
    const __half* Wt1  = (const __half*)pw1;
    const __half* Wt2  = (const __half*)pw2;
    const __half* Wtm1 = (const __half*)pm1;
    const __half* Wtm2 = (const __half*)pm2;

    cudaMemsetAsync(pcc, 0, (2 * NN + 4) * sizeof(int));

    k_prep<<<1, 1024>>>(W1, W2, Wm1, Wm2);                                  // 1
    k_cvtx<<<3125, 256>>>(x, bufA);                                         // 2
    k_csr <<<CSRG, CSRT>>>(ei);                                             // 3
    k_gemmTC<8, false, false, false><<<GEMMG, 256>>>((const __half*)bufA, Wt1, nullptr, bufB);   // 4: PROFILED
    k_agg<true><<<3125, 256>>>(bufB, b1, bufA);                             // 5
    k_gemmTC<8, false, false, false><<<GEMMG, 256>>>((const __half*)bufA, Wt2, nullptr, bufB);   // 6
    k_agg<false><<<3125, 256>>>(bufB, b2, bufA);                            // 7
    k_gemmTC<8, true, true, false><<<GEMMG, 256>>>((const __half*)bufA, Wtm1, bm1, bufB);        // 8
    k_gemmTC<5, true, false, true><<<GEMMG, 256>>>((const __half*)bufB, Wtm2, bm2, out);         // 9
}

// round 12
// speedup vs baseline: 3.4052x; 1.2226x over previous
#include <cuda_runtime.h>
#include <cuda_fp16.h>

#define NN 100000
#define EE 1000000
#define CC 64
#define OUTC 40
#define NB 98          // ceil(NN/1024)
#define E4 (EE/4)
#define CSRG 592       // resident grid: 148 SMs x 8 blocks guaranteed by launch_bounds
#define CSRT 256
#define NTILES 6250    // NN/16
#define GEMMG 782      // ceil(NTILES/8) -> 1 tile per warp

typedef unsigned long long ull;

// ---------------- device scratch ----------------
__device__ int     g_cc[2 * NN + 4];   // [0,NN) counts ; [NN,2NN) cursors ; [2NN] barrier
__device__ int     g_rowptr[NN];
__device__ int     g_bsum[NB];
__device__ int2    g_edge[EE];         // {src*8 (uint4 idx), bitcast(norm)} grouped by dst
__device__ __half2 g_bufA[NN * CC / 2];
__device__ __half2 g_bufB[NN * CC / 2];
__device__ __half  g_Wt1[CC * CC];     // transposed fp16 weights [n][k]
__device__ __half  g_Wt2[CC * CC];
__device__ __half  g_Wtm1[CC * CC];
__device__ __half  g_Wtm2[OUTC * CC];

// ---------------- fused prep: x fp32->fp16 rows + weight transpose ----------------
__global__ __launch_bounds__(256)
void k_prepall(const float* __restrict__ x, __half2* __restrict__ out,
               const float* __restrict__ W1, const float* __restrict__ W2,
               const float* __restrict__ Wm1, const float* __restrict__ Wm2) {
    int b = blockIdx.x, tid = threadIdx.x;
    if (b < 3125) {
        int i = b * 256 + tid;                 // one uint4 (8 halfs) per thread
        const float4* x4 = (const float4*)x;
        float4 f0 = x4[2 * i], f1 = x4[2 * i + 1];
        __half2 h0 = __floats2half2_rn(f0.x, f0.y);
        __half2 h1 = __floats2half2_rn(f0.z, f0.w);
        __half2 h2 = __floats2half2_rn(f1.x, f1.y);
        __half2 h3 = __floats2half2_rn(f1.z, f1.w);
        uint4 o;
        o.x = *(unsigned*)&h0; o.y = *(unsigned*)&h1;
        o.z = *(unsigned*)&h2; o.w = *(unsigned*)&h3;
        ((uint4*)out)[i] = o;
    } else {
        int which = b - 3125;
        if (which < 3) {
            const float* W = (which == 0) ? W1 : (which == 1) ? W2 : Wm1;
            __half* Wt = (which == 0) ? g_Wt1 : (which == 1) ? g_Wt2 : g_Wtm1;
            for (int i = tid; i < CC * CC; i += 256) {
                int n = i >> 6, k = i & 63;
                Wt[i] = __float2half(W[k * CC + n]);
            }
        } else {
            for (int i = tid; i < OUTC * CC; i += 256) {
                int n = i >> 6, k = i & 63;
                g_Wtm2[i] = __float2half(Wm2[k * OUTC + n]);
            }
        }
    }
}

// ---------------- fused CSR build: hist -> scan -> fill, one kernel ----------------
__device__ __forceinline__ void gsync(int target) {
    __threadfence();
    __syncthreads();
    if (threadIdx.x == 0) {
        atomicAdd(&g_cc[2 * NN], 1);
        while (atomicAdd(&g_cc[2 * NN], 0) < target) __nanosleep(64);
        __threadfence();
    }
    __syncthreads();
}

__device__ __forceinline__ void fill_one(int s, int d) {
    float ns = rsqrtf((float)g_cc[s] + 1.0f);
    float nd = rsqrtf((float)g_cc[d] + 1.0f);
    int pos = g_rowptr[d] + g_bsum[d >> 10] + atomicAdd(&g_cc[NN + d], 1);
    g_edge[pos] = make_int2(s * 8, __float_as_int(ns * nd));
}

__global__ __launch_bounds__(CSRT, 8)
void k_csr(const void* __restrict__ ei) {
    __shared__ int s_is64;
    __shared__ int s_scan[CSRT];
    int tid = threadIdx.x, bid = blockIdx.x;

    if (tid == 0) {
        const long long* p = (const long long*)ei;
        int ok = 1;
#pragma unroll
        for (int i = 0; i < 16; i++) { long long v = p[i]; if (v < 0 || v >= NN) ok = 0; }
        s_is64 = ok;
    }
    __syncthreads();
    int is64 = s_is64;

    for (int i = bid * CSRT + tid; i < E4; i += CSRG * CSRT) {
        if (!is64) {
            int4 d = ((const int4*)ei)[E4 + i];
            atomicAdd(&g_cc[d.x], 1); atomicAdd(&g_cc[d.y], 1);
            atomicAdd(&g_cc[d.z], 1); atomicAdd(&g_cc[d.w], 1);
        } else {
            const long long* p = (const long long*)ei;
#pragma unroll
            for (int j = 0; j < 4; j++) atomicAdd(&g_cc[(int)p[EE + 4 * i + j]], 1);
        }
    }
    gsync(CSRG);

    if (bid < NB) {
        int base = bid * 1024 + tid * 4;
        int c0 = 0, c1 = 0, c2 = 0, c3 = 0;
        if (base + 0 < NN) c0 = g_cc[base + 0];
        if (base + 1 < NN) c1 = g_cc[base + 1];
        if (base + 2 < NN) c2 = g_cc[base + 2];
        if (base + 3 < NN) c3 = g_cc[base + 3];
        int v = c0 + c1 + c2 + c3;
        s_scan[tid] = v;
        __syncthreads();
        for (int off = 1; off < CSRT; off <<= 1) {
            int t2 = (tid >= off) ? s_scan[tid - off] : 0;
            __syncthreads();
            s_scan[tid] += t2;
            __syncthreads();
        }
        int incl = s_scan[tid];
        int excl = incl - v;
        if (base + 0 < NN) g_rowptr[base + 0] = excl;
        if (base + 1 < NN) g_rowptr[base + 1] = excl + c0;
        if (base + 2 < NN) g_rowptr[base + 2] = excl + c0 + c1;
        if (base + 3 < NN) g_rowptr[base + 3] = excl + c0 + c1 + c2;
        if (tid == CSRT - 1) g_bsum[bid] = incl;
    }
    gsync(2 * CSRG);

    if (bid == 0) {
        int lane = tid & 31, w = tid >> 5;
        int v = (tid < NB) ? g_bsum[tid] : 0;
        int x = v;
#pragma unroll
        for (int off = 1; off < 32; off <<= 1) {
            int y = __shfl_up_sync(0xffffffffu, x, off);
            if (lane >= off) x += y;
        }
        if (lane == 31 && w < 4) s_scan[w] = x;
        __syncthreads();
        if (tid < NB) {
            int woff = 0;
#pragma unroll
            for (int q = 0; q < 4; q++) if (q < w) woff += s_scan[q];
            g_bsum[tid] = x - v + woff;
        }
    }
    gsync(3 * CSRG);

    for (int i = bid * CSRT + tid; i < E4; i += CSRG * CSRT) {
        if (!is64) {
            int4 s4 = ((const int4*)ei)[i];
            int4 d4 = ((const int4*)ei)[E4 + i];
            fill_one(s4.x, d4.x); fill_one(s4.y, d4.y);
            fill_one(s4.z, d4.z); fill_one(s4.w, d4.w);
        } else {
            const long long* p = (const long long*)ei;
#pragma unroll
            for (int j = 0; j < 4; j++)
                fill_one((int)p[4 * i + j], (int)p[EE + 4 * i + j]);
        }
    }
}

// ---------------- tensor-core GEMM with smem + ldmatrix ----------------
__device__ __forceinline__ unsigned scvt(const void* p) {
    return (unsigned)__cvta_generic_to_shared(p);
}
__device__ __forceinline__ void ldsm4(unsigned& r0, unsigned& r1, unsigned& r2,
                                      unsigned& r3, unsigned addr) {
    asm volatile("ldmatrix.sync.aligned.m8n8.x4.shared.b16 {%0,%1,%2,%3}, [%4];"
                 : "=r"(r0), "=r"(r1), "=r"(r2), "=r"(r3) : "r"(addr));
}
__device__ __forceinline__ void ldsm2(unsigned& r0, unsigned& r1, unsigned addr) {
    asm volatile("ldmatrix.sync.aligned.m8n8.x2.shared.b16 {%0,%1}, [%2];"
                 : "=r"(r0), "=r"(r1) : "r"(addr));
}
__device__ __forceinline__ void mma16816(float c[4], unsigned a0, unsigned a1,
                                         unsigned a2, unsigned a3,
                                         unsigned b0, unsigned b1) {
    asm volatile(
        "mma.sync.aligned.m16n8k16.row.col.f32.f16.f16.f32 "
        "{%0,%1,%2,%3},{%4,%5,%6,%7},{%8,%9},{%0,%1,%2,%3};"
        : "+f"(c[0]), "+f"(c[1]), "+f"(c[2]), "+f"(c[3])
        : "r"(a0), "r"(a1), "r"(a2), "r"(a3), "r"(b0), "r"(b1));
}

// out[N, NT*8] = A[N,64](f16) @ Wt^T ; f32 accum. One 16-row tile per warp.
template <int NT, bool BIAS, bool RELU, bool OUTF32>
__global__ __launch_bounds__(256)
void k_gemmTC(const __half* __restrict__ A, const __half* __restrict__ Wt,
              const float* __restrict__ bias, void* __restrict__ outv) {
    const int NCOLS = NT * 8;
    __shared__ uint4 Bs[NT * 8 * 8];      // NT*8 rows x 8 swizzled 16B chunks
    __shared__ uint4 As[8][128];          // per-warp 16 rows x 8 swizzled chunks
    int tid = threadIdx.x, lane = tid & 31, wid = tid >> 5;

    const uint4* W4 = (const uint4*)Wt;
    for (int i = tid; i < NT * 64; i += 256) {
        int r = i >> 3, c = i & 7;
        Bs[r * 8 + (c ^ (r & 7))] = W4[i];
    }
    __syncthreads();

    int tile = blockIdx.x * 8 + wid;
    if (tile >= NTILES) return;

    // coalesced A tile -> swizzled smem
    const uint4* A4 = (const uint4*)(A + (size_t)tile * 16 * CC);
#pragma unroll
    for (int j = 0; j < 4; j++) {
        int i = j * 32 + lane;
        int r = i >> 3, c = i & 7;
        As[wid][r * 8 + (c ^ (r & 7))] = A4[i];
    }
    __syncwarp();

    int ri = lane & 7, m = lane >> 3;     // ldmatrix row-provider decomposition
    float c_[NT][4];
#pragma unroll
    for (int nt = 0; nt < NT; nt++) { c_[nt][0] = c_[nt][1] = c_[nt][2] = c_[nt][3] = 0.f; }

#pragma unroll
    for (int ks = 0; ks < 4; ks++) {
        // A fragment: mats {r0-7,k0-7},{r8-15,k0-7},{r0-7,k8-15},{r8-15,k8-15}
        int ar = (m & 1) ? (8 + ri) : ri;
        int ac = 2 * ks + (m >> 1);
        unsigned a0, a1, a2, a3;
        ldsm4(a0, a1, a2, a3, scvt(&As[wid][ar * 8 + (ac ^ (ar & 7))]));

        unsigned b[NT][2];
#pragma unroll
        for (int ntp = 0; ntp < NT / 2; ntp++) {
            // mats: {n0-7,k0-7},{n0-7,k8-15},{n8-15,k0-7},{n8-15,k8-15}
            int br = 16 * ntp + ((m >> 1) ? 8 : 0) + ri;
            int bc = 2 * ks + (m & 1);
            unsigned r0, r1, r2, r3;
            ldsm4(r0, r1, r2, r3, scvt(&Bs[br * 8 + (bc ^ (br & 7))]));
            b[2 * ntp][0] = r0; b[2 * ntp][1] = r1;
            b[2 * ntp + 1][0] = r2; b[2 * ntp + 1][1] = r3;
        }
        if (NT & 1) {
            int m2 = m & 1;               // lanes 16-31 mirror 0-15 (addrs ignored)
            int br = (NT - 1) * 8 + ri;
            int bc = 2 * ks + m2;
            unsigned r0, r1;
            ldsm2(r0, r1, scvt(&Bs[br * 8 + (bc ^ (br & 7))]));
            b[NT - 1][0] = r0; b[NT - 1][1] = r1;
        }

#pragma unroll
        for (int nt = 0; nt < NT; nt++)
            mma16816(c_[nt], a0, a1, a2, a3, b[nt][0], b[nt][1]);
    }

    int g = lane >> 2, t = lane & 3;
    int r0 = tile * 16 + g;
#pragma unroll
    for (int nt = 0; nt < NT; nt++) {
        int col = nt * 8 + 2 * t;
        float c0 = c_[nt][0], c1 = c_[nt][1], c2 = c_[nt][2], c3 = c_[nt][3];
        if (BIAS) {
            float bb0 = __ldg(bias + col), bb1 = __ldg(bias + col + 1);
            c0 += bb0; c1 += bb1; c2 += bb0; c3 += bb1;
        }
        if (RELU) {
            c0 = fmaxf(c0, 0.f); c1 = fmaxf(c1, 0.f);
            c2 = fmaxf(c2, 0.f); c3 = fmaxf(c3, 0.f);
        }
        if (OUTF32) {
            float* o = (float*)outv;
            *(float2*)(o + (size_t)r0 * NCOLS + col)       = make_float2(c0, c1);
            *(float2*)(o + (size_t)(r0 + 8) * NCOLS + col) = make_float2(c2, c3);
        } else {
            __half* o = (__half*)outv;
            *(__half2*)(o + (size_t)r0 * NCOLS + col)       = __floats2half2_rn(c0, c1);
            *(__half2*)(o + (size_t)(r0 + 8) * NCOLS + col) = __floats2half2_rn(c2, c3);
        }
    }
}

// ---------------- aggregation: 4 nodes/warp, 8 lanes/node, fp16 in -> fp16 out ----------------
template <bool RELU>
__global__ __launch_bounds__(256)
void k_agg(const __half2* __restrict__ hf, const float* __restrict__ bias,
           __half2* __restrict__ out) {
    const uint4* hf4 = (const uint4*)hf;
    int node = blockIdx.x * 32 + (threadIdx.x >> 3);
    int l = threadIdx.x & 7;

    int deg = g_cc[node];
    float self = __frcp_rn((float)deg + 1.0f);

    float a0, a1, a2, a3, a4, a5, a6, a7;
    {
        uint4 v = hf4[node * 8 + l];
        const __half2* hp = (const __half2*)&v;
        float2 f0 = __half22float2(hp[0]), f1 = __half22float2(hp[1]);
        float2 f2 = __half22float2(hp[2]), f3 = __half22float2(hp[3]);
        a0 = f0.x * self; a1 = f0.y * self;
        a2 = f1.x * self; a3 = f1.y * self;
        a4 = f2.x * self; a5 = f2.y * self;
        a6 = f3.x * self; a7 = f3.y * self;
    }

    int beg = g_rowptr[node] + g_bsum[node >> 10];
    int end = (node + 1 == NN) ? EE : (g_rowptr[node + 1] + g_bsum[(node + 1) >> 10]);

    int e = beg;
    for (; e + 1 < end; e += 2) {
        int2 m0 = g_edge[e], m1 = g_edge[e + 1];
        uint4 v0 = hf4[m0.x + l];
        uint4 v1 = hf4[m1.x + l];
        float n0 = __int_as_float(m0.y);
        float n1 = __int_as_float(m1.y);
        {
            const __half2* hp = (const __half2*)&v0;
            float2 f0 = __half22float2(hp[0]), f1 = __half22float2(hp[1]);
            float2 f2 = __half22float2(hp[2]), f3 = __half22float2(hp[3]);
            a0 = fmaf(f0.x, n0, a0); a1 = fmaf(f0.y, n0, a1);
            a2 = fmaf(f1.x, n0, a2); a3 = fmaf(f1.y, n0, a3);
            a4 = fmaf(f2.x, n0, a4); a5 = fmaf(f2.y, n0, a5);
            a6 = fmaf(f3.x, n0, a6); a7 = fmaf(f3.y, n0, a7);
        }
        {
            const __half2* hp = (const __half2*)&v1;
            float2 f0 = __half22float2(hp[0]), f1 = __half22float2(hp[1]);
            float2 f2 = __half22float2(hp[2]), f3 = __half22float2(hp[3]);
            a0 = fmaf(f0.x, n1, a0); a1 = fmaf(f0.y, n1, a1);
            a2 = fmaf(f1.x, n1, a2); a3 = fmaf(f1.y, n1, a3);
            a4 = fmaf(f2.x, n1, a4); a5 = fmaf(f2.y, n1, a5);
            a6 = fmaf(f3.x, n1, a6); a7 = fmaf(f3.y, n1, a7);
        }
    }
    if (e < end) {
        int2 m = g_edge[e];
        uint4 v = hf4[m.x + l];
        float nm = __int_as_float(m.y);
        const __half2* hp = (const __half2*)&v;
        float2 f0 = __half22float2(hp[0]), f1 = __half22float2(hp[1]);
        float2 f2 = __half22float2(hp[2]), f3 = __half22float2(hp[3]);
        a0 = fmaf(f0.x, nm, a0); a1 = fmaf(f0.y, nm, a1);
        a2 = fmaf(f1.x, nm, a2); a3 = fmaf(f1.y, nm, a3);
        a4 = fmaf(f2.x, nm, a4); a5 = fmaf(f2.y, nm, a5);
        a6 = fmaf(f3.x, nm, a6); a7 = fmaf(f3.y, nm, a7);
    }

    const float4* b4 = (const float4*)(bias + l * 8);
    float4 bA = b4[0], bB = b4[1];
    a0 += bA.x; a1 += bA.y; a2 += bA.z; a3 += bA.w;
    a4 += bB.x; a5 += bB.y; a6 += bB.z; a7 += bB.w;
    if (RELU) {
        a0 = fmaxf(a0, 0.f); a1 = fmaxf(a1, 0.f);
        a2 = fmaxf(a2, 0.f); a3 = fmaxf(a3, 0.f);
        a4 = fmaxf(a4, 0.f); a5 = fmaxf(a5, 0.f);
        a6 = fmaxf(a6, 0.f); a7 = fmaxf(a7, 0.f);
    }
    __half2 h0 = __floats2half2_rn(a0, a1);
    __half2 h1 = __floats2half2_rn(a2, a3);
    __half2 h2 = __floats2half2_rn(a4, a5);
    __half2 h3 = __floats2half2_rn(a6, a7);
    uint4 o;
    o.x = *(unsigned*)&h0; o.y = *(unsigned*)&h1;
    o.z = *(unsigned*)&h2; o.w = *(unsigned*)&h3;
    ((uint4*)out)[node * 8 + l] = o;
}

// ---------------- launcher ----------------
extern "C" void kernel_launch(void* const* d_in, const int* in_sizes, int n_in,
                              void* d_out, int out_size) {
    const float* x   = (const float*)d_in[0];
    const void*  ei  = d_in[1];
    const float* W1  = (const float*)d_in[2];
    const float* b1  = (const float*)d_in[3];
    const float* W2  = (const float*)d_in[4];
    const float* b2  = (const float*)d_in[5];
    const float* Wm1 = (const float*)d_in[6];
    const float* bm1 = (const float*)d_in[7];
    const float* Wm2 = (const float*)d_in[8];
    const float* bm2 = (const float*)d_in[9];
    float* out = (float*)d_out;

    void *pcc = nullptr, *pa = nullptr, *pb = nullptr;
    void *pw1 = nullptr, *pw2 = nullptr, *pm1 = nullptr, *pm2 = nullptr;
    cudaGetSymbolAddress(&pcc, g_cc);
    cudaGetSymbolAddress(&pa, g_bufA);
    cudaGetSymbolAddress(&pb, g_bufB);
    cudaGetSymbolAddress(&pw1, g_Wt1);
    cudaGetSymbolAddress(&pw2, g_Wt2);
    cudaGetSymbolAddress(&pm1, g_Wtm1);
    cudaGetSymbolAddress(&pm2, g_Wtm2);
    __half2* bufA = (__half2*)pa;
    __half2* bufB = (__half2*)pb;
    const __half* Wt1  = (const __half*)pw1;
    const __half* Wt2  = (const __half*)pw2;
    const __half* Wtm1 = (const __half*)pm1;
    const __half* Wtm2 = (const __half*)pm2;

    cudaMemsetAsync(pcc, 0, (2 * NN + 4) * sizeof(int));

    k_prepall<<<3129, 256>>>(x, bufA, W1, W2, Wm1, Wm2);                    // 1
    k_csr <<<CSRG, CSRT>>>(ei);                                             // 2
    k_gemmTC<8, false, false, false><<<GEMMG, 256>>>((const __half*)bufA, Wt1, nullptr, bufB);   // 3
    k_agg<true><<<3125, 256>>>(bufB, b1, bufA);                             // 4: PROFILED
    k_gemmTC<8, false, false, false><<<GEMMG, 256>>>((const __half*)bufA, Wt2, nullptr, bufB);   // 5
    k_agg<false><<<3125, 256>>>(bufB, b2, bufA);                            // 6
    k_gemmTC<8, true, true, false><<<GEMMG, 256>>>((const __half*)bufA, Wtm1, bm1, bufB);        // 7
    k_gemmTC<5, true, false, true><<<GEMMG, 256>>>((const __half*)bufB, Wtm2, bm2, out);         // 8
}